// round 11
// baseline (speedup 1.0000x reference)
#include <cuda_runtime.h>
#include <math.h>

// Problem constants (fixed-shape benchmark)
#define NN 50000
#define HH 16
#define RR 32
#define CC 8
#define EE 1600000
#define CAP 80   // max degree slot capacity (Poisson(32); P(exceed) ~ 1e-7, guarded)

// Scratch (device globals; no allocation allowed)
__device__ float g_cnt[NN * RR];   // counts, then inverted in-place -> 1/max(cnt,1)
__device__ int   g_cur[NN];        // per-node fill cursor (= degree after build)
__device__ int   g_ep[NN * CAP];   // 4B records: src | r<<16, slotted per node (16 MB)
__device__ float g_x[NN * HH];     // layer-1 node features

// ---------------------------------------------------------------- (0) zero cnt + cur
__global__ void k_zero() {
    int i = blockIdx.x * blockDim.x + threadIdx.x;
    int nc = NN * RR / 4;
    if (i < nc) ((float4*)g_cnt)[i] = make_float4(0.f, 0.f, 0.f, 0.f);
    else if (i < nc + NN / 4) ((int4*)g_cur)[i - nc] = make_int4(0, 0, 0, 0);
}

// ---------------------------------------------------------------- (1) build: count + slot-scatter in one pass
__global__ void k_build(const int* __restrict__ ei, const int* __restrict__ et) {
    int e = blockIdx.x * blockDim.x + threadIdx.x;
    if (e >= EE) return;
    int src = __ldg(ei + e);
    int dst = __ldg(ei + EE + e);
    int r   = __ldg(et + e);
    atomicAdd(&g_cnt[dst * RR + r], 1.0f);
    int pos = atomicAdd(&g_cur[dst], 1);
    if (pos < CAP) g_ep[dst * CAP + pos] = src | (r << 16);
}

// ---------------------------------------------------------------- (2) invert counts in place
__global__ void k_inv() {
    int i = blockIdx.x * blockDim.x + threadIdx.x;
    if (i >= NN * RR / 4) return;
    float4 v = ((float4*)g_cnt)[i];
    v.x = __frcp_rn(fmaxf(v.x, 1.f));
    v.y = __frcp_rn(fmaxf(v.y, 1.f));
    v.z = __frcp_rn(fmaxf(v.z, 1.f));
    v.w = __frcp_rn(fmaxf(v.w, 1.f));
    ((float4*)g_cnt)[i] = v;
}

// ---------------------------------------------------------------- (3) layer 1: CSR, 16 lanes/node, fused act
__global__ void __launch_bounds__(256)
k_layer1(const float* __restrict__ w1, const float* __restrict__ root1,
         const float* __restrict__ b1) {
    int tid = blockIdx.x * 256 + threadIdx.x;
    int n = tid >> 4;
    int f = tid & 15;
    if (n >= NN) return;
    int lane = threadIdx.x & 31;
    unsigned gmask = (lane & 16) ? 0xFFFF0000u : 0x0000FFFFu;

    int m = min(__ldg(&g_cur[n]), CAP);
    // preload inv row: lane f holds inv[n][f], inv[n][16+f]  (coalesced)
    float inv_lo = g_cnt[n * RR + f];
    float inv_hi = g_cnt[n * RR + 16 + f];
    const int* ep = g_ep + n * CAP;

    float acc = 0.f;
    int k = 0;
    for (; k + 8 <= m; k += 8) {
        int4 a = __ldg((const int4*)(ep + k));
        int4 b = __ldg((const int4*)(ep + k + 4));
        int pk[8] = {a.x, a.y, a.z, a.w, b.x, b.y, b.z, b.w};
        float wv[8];
        #pragma unroll
        for (int j = 0; j < 8; j++) {
            int r = pk[j] >> 16, s = pk[j] & 0xFFFF;
            wv[j] = __ldg(&w1[((r * NN + s) << 4) + f]);
        }
        #pragma unroll
        for (int j = 0; j < 8; j++) {
            int r = pk[j] >> 16;
            float iv = __shfl_sync(gmask, (r < 16) ? inv_lo : inv_hi, r & 15, 16);
            acc += wv[j] * iv;
        }
    }
    for (; k < m; k++) {
        int v = __ldg(ep + k);
        int r = v >> 16, s = v & 0xFFFF;
        float w = __ldg(&w1[((r * NN + s) << 4) + f]);
        float iv = __shfl_sync(gmask, (r < 16) ? inv_lo : inv_hi, r & 15, 16);
        acc += w * iv;
    }
    float v = acc + __ldg(&root1[(n << 4) + f]) + __ldg(&b1[f]);
    g_x[(n << 4) + f] = fmaxf(v, 0.f);
}

// ---------------------------------------------------------------- (4) layer 2: CSR recompute, 8 lanes/node, fused epilogue
__global__ void __launch_bounds__(256)
k_layer2(const float* __restrict__ w2, const float* __restrict__ root2,
         const float* __restrict__ b2, float* __restrict__ out) {
    __shared__ float sw[HH * CC * 33];   // [ (h*8+c)*33 + r ]
    __shared__ float sr2[HH * CC];
    __shared__ float sb2[CC];
    for (int i = threadIdx.x; i < RR * HH * CC; i += 256) {
        int r  = i >> 7;
        int hc = i & 127;
        sw[hc * 33 + r] = w2[i];
    }
    if (threadIdx.x < HH * CC) sr2[threadIdx.x] = root2[threadIdx.x];
    if (threadIdx.x < CC) sb2[threadIdx.x] = b2[threadIdx.x];
    __syncthreads();

    int tid = blockIdx.x * 256 + threadIdx.x;
    int n = tid >> 3;
    int c = tid & 7;
    bool valid = (n < NN);
    if (!valid) n = NN - 1;             // keep warp whole for shfl
    int lane = threadIdx.x & 31;
    unsigned gmask = 0xFFu << (lane & 24);

    int m = min(__ldg(&g_cur[n]), CAP);
    // preload inv row: lane c holds inv[n][c + 8j] for j=0..3 (coalesced)
    float iv0 = g_cnt[n * RR + c];
    float iv1 = g_cnt[n * RR + 8 + c];
    float iv2 = g_cnt[n * RR + 16 + c];
    float iv3 = g_cnt[n * RR + 24 + c];
    const int* ep = g_ep + n * CAP;

    float acc = 0.f;
    for (int k = 0; k < m; k++) {
        int v = __ldg(ep + k);
        int r = v >> 16, s = v & 0xFFFF;
        int j = r >> 3;
        float sel = (j == 0) ? iv0 : (j == 1) ? iv1 : (j == 2) ? iv2 : iv3;
        float iv = __shfl_sync(gmask, sel, r & 7, 8);
        const float4* xp = (const float4*)(g_x + (s << 4));
        float4 x0 = __ldg(&xp[0]), x1 = __ldg(&xp[1]);
        float4 x2 = __ldg(&xp[2]), x3 = __ldg(&xp[3]);
        int base = c * 33 + r;
        float dot;
        dot  = x0.x * sw[base +  0*264] + x0.y * sw[base +  1*264]
             + x0.z * sw[base +  2*264] + x0.w * sw[base +  3*264];
        dot += x1.x * sw[base +  4*264] + x1.y * sw[base +  5*264]
             + x1.z * sw[base +  6*264] + x1.w * sw[base +  7*264];
        dot += x2.x * sw[base +  8*264] + x2.y * sw[base +  9*264]
             + x2.z * sw[base + 10*264] + x2.w * sw[base + 11*264];
        dot += x3.x * sw[base + 12*264] + x3.y * sw[base + 13*264]
             + x3.z * sw[base + 14*264] + x3.w * sw[base + 15*264];
        acc += dot * iv;
    }

    // + x[n] @ root2 + b2
    const float4* xp = (const float4*)(g_x + (n << 4));
    float o = acc + sb2[c];
    #pragma unroll
    for (int i4 = 0; i4 < 4; i4++) {
        float4 xv = __ldg(&xp[i4]);
        o += xv.x * sr2[(i4 * 4 + 0) * CC + c];
        o += xv.y * sr2[(i4 * 4 + 1) * CC + c];
        o += xv.z * sr2[(i4 * 4 + 2) * CC + c];
        o += xv.w * sr2[(i4 * 4 + 3) * CC + c];
    }

    // log_softmax across the 8-lane class group
    float mx = o;
    #pragma unroll
    for (int d = 1; d < 8; d <<= 1)
        mx = fmaxf(mx, __shfl_xor_sync(0xFFFFFFFF, mx, d));
    float s = expf(o - mx);
    #pragma unroll
    for (int d = 1; d < 8; d <<= 1)
        s += __shfl_xor_sync(0xFFFFFFFF, s, d);
    if (valid) out[n * CC + c] = o - mx - logf(s);
}

// ---------------------------------------------------------------- launch
extern "C" void kernel_launch(void* const* d_in, const int* in_sizes, int n_in,
                              void* d_out, int out_size) {
    const int*   ei    = (const int*)  d_in[0];  // [2, E]
    const int*   et    = (const int*)  d_in[1];  // [E]
    const float* w1    = (const float*)d_in[2];  // [R, N, H]
    const float* root1 = (const float*)d_in[3];  // [N, H]
    const float* b1    = (const float*)d_in[4];  // [H]
    const float* w2    = (const float*)d_in[5];  // [R, H, C]
    const float* root2 = (const float*)d_in[6];  // [H, C]
    const float* b2    = (const float*)d_in[7];  // [C]
    float* out = (float*)d_out;                  // [N, C]

    int zt = NN * RR / 4 + NN / 4;
    k_zero  <<<(zt + 255) / 256, 256>>>();
    k_build <<<(EE + 255) / 256, 256>>>(ei, et);
    k_inv   <<<(NN * RR / 4 + 255) / 256, 256>>>();
    k_layer1<<<(NN * 16 + 255) / 256, 256>>>(w1, root1, b1);   // idx 3 -> profiled
    k_layer2<<<(NN * 8 + 255) / 256, 256>>>(w2, root2, b2, out);
}

// round 12
// speedup vs baseline: 1.3564x; 1.3564x over previous
#include <cuda_runtime.h>
#include <math.h>

// Problem constants (fixed-shape benchmark)
#define NN 50000
#define HH 16
#define RR 32
#define CC 8
#define EE 1600000
#define CAP 80   // slot capacity; deg ~ Poisson(32), P(exceed) ~ 1e-7, guarded

// Scratch (device globals; no allocation allowed)
__device__ int   g_cur[NN];          // per-node fill cursor (= degree after build)
__device__ int   g_ep[NN * CAP];     // 4B records: src | r<<16 (16 MB)
__device__ float g_inv[NN * RR];     // 1/max(cnt,1), produced by layer1 (12.8 MB)
__device__ float g_x[NN * HH];       // layer-1 node features
__device__ float g_xw[RR * NN * CC]; // per-relation transformed feats (51.2 MB)

// ---------------------------------------------------------------- (0) zero cursors
__global__ void k_zero() {
    int i = blockIdx.x * blockDim.x + threadIdx.x;
    if (i < NN / 4) ((int4*)g_cur)[i] = make_int4(0, 0, 0, 0);
}

// ---------------------------------------------------------------- (1) build slotted CSR (1 atomic + 1 store per edge)
__global__ void k_build(const int* __restrict__ ei, const int* __restrict__ et) {
    int e = blockIdx.x * blockDim.x + threadIdx.x;
    if (e >= EE) return;
    int src = __ldg(ei + e);
    int dst = __ldg(ei + EE + e);
    int r   = __ldg(et + e);
    int pos = atomicAdd(&g_cur[dst], 1);
    if (pos < CAP) g_ep[dst * CAP + pos] = src | (r << 16);
}

// ---------------------------------------------------------------- (2) layer 1: count + gather, 16 lanes/node, fused act
__global__ void __launch_bounds__(256)
k_layer1(const float* __restrict__ w1, const float* __restrict__ root1,
         const float* __restrict__ b1) {
    int tid = blockIdx.x * 256 + threadIdx.x;
    int n = tid >> 4;
    int f = tid & 15;
    if (n >= NN) return;
    int lane = threadIdx.x & 31;
    unsigned gmask = (lane & 16) ? 0xFFFF0000u : 0x0000FFFFu;

    int m = min(__ldg(&g_cur[n]), CAP);
    const int* ep = g_ep + n * CAP;

    // pass A: per-lane relation histogram (lane f counts r==f and r==f+16)
    int clo = 0, chi = 0;
    int k = 0;
    for (; k + 4 <= m; k += 4) {
        int4 a = __ldg((const int4*)(ep + k));
        int r0 = a.x >> 16, r1 = a.y >> 16, r2 = a.z >> 16, r3 = a.w >> 16;
        clo += (r0 == f) + (r1 == f) + (r2 == f) + (r3 == f);
        int fh = f + 16;
        chi += (r0 == fh) + (r1 == fh) + (r2 == fh) + (r3 == fh);
    }
    for (; k < m; k++) {
        int r = __ldg(ep + k) >> 16;
        clo += (r == f);
        chi += (r == f + 16);
    }
    float inv_lo = __frcp_rn(fmaxf((float)clo, 1.f));
    float inv_hi = __frcp_rn(fmaxf((float)chi, 1.f));
    g_inv[n * RR + f]      = inv_lo;   // coalesced; consumed by layer2
    g_inv[n * RR + 16 + f] = inv_hi;

    // pass B: w1 gather + weighted accumulate (records now L1-hot)
    float acc = 0.f;
    k = 0;
    for (; k + 8 <= m; k += 8) {
        int4 a = __ldg((const int4*)(ep + k));
        int4 b = __ldg((const int4*)(ep + k + 4));
        int pk[8] = {a.x, a.y, a.z, a.w, b.x, b.y, b.z, b.w};
        float wv[8];
        #pragma unroll
        for (int j = 0; j < 8; j++) {
            int r = pk[j] >> 16, s = pk[j] & 0xFFFF;
            wv[j] = __ldg(&w1[((r * NN + s) << 4) + f]);
        }
        #pragma unroll
        for (int j = 0; j < 8; j++) {
            int r = pk[j] >> 16;
            float iv = __shfl_sync(gmask, (r < 16) ? inv_lo : inv_hi, r & 15, 16);
            acc += wv[j] * iv;
        }
    }
    for (; k < m; k++) {
        int v = __ldg(ep + k);
        int r = v >> 16, s = v & 0xFFFF;
        float w = __ldg(&w1[((r * NN + s) << 4) + f]);
        float iv = __shfl_sync(gmask, (r < 16) ? inv_lo : inv_hi, r & 15, 16);
        acc += w * iv;
    }
    float v = acc + __ldg(&root1[(n << 4) + f]) + __ldg(&b1[f]);
    g_x[(n << 4) + f] = fmaxf(v, 0.f);
}

// ---------------------------------------------------------------- (3) xw materialization: xw[r,n,:] = x[n,:] @ w2[r]
__global__ void __launch_bounds__(256)
k_xw(const float* __restrict__ w2) {
    __shared__ float sw[2 * HH * CC];
    int idx0 = blockIdx.x * 256;
    int r0 = idx0 / NN;
    int r1 = (idx0 + 255) / NN;
    int nrel = r1 - r0 + 1;
    for (int i = threadIdx.x; i < nrel * HH * CC; i += 256)
        sw[i] = w2[r0 * HH * CC + i];
    __syncthreads();

    int idx = idx0 + threadIdx.x;       // over RR*NN
    if (idx >= RR * NN) return;
    int r = idx / NN;
    int n = idx - r * NN;
    const float4* xp = (const float4*)(g_x + n * HH);
    const float* w = sw + (r - r0) * HH * CC;

    float acc[CC];
    #pragma unroll
    for (int c = 0; c < CC; c++) acc[c] = 0.f;

    #pragma unroll
    for (int i4 = 0; i4 < 4; i4++) {
        float4 xv = xp[i4];
        float xs[4] = {xv.x, xv.y, xv.z, xv.w};
        #pragma unroll
        for (int j = 0; j < 4; j++) {
            int h = i4 * 4 + j;
            #pragma unroll
            for (int c = 0; c < CC; c++)
                acc[c] += xs[j] * w[h * CC + c];
        }
    }
    float4* op = (float4*)(g_xw + (size_t)idx * CC);
    op[0] = make_float4(acc[0], acc[1], acc[2], acc[3]);
    op[1] = make_float4(acc[4], acc[5], acc[6], acc[7]);
}

// ---------------------------------------------------------------- (4) layer 2: xw gather, 8 lanes/node, fused epilogue
__global__ void __launch_bounds__(256)
k_layer2(const float* __restrict__ root2, const float* __restrict__ b2,
         float* __restrict__ out) {
    __shared__ float sr2[HH * CC];
    __shared__ float sb2[CC];
    if (threadIdx.x < HH * CC) sr2[threadIdx.x] = root2[threadIdx.x];
    if (threadIdx.x < CC) sb2[threadIdx.x] = b2[threadIdx.x];
    __syncthreads();

    int tid = blockIdx.x * 256 + threadIdx.x;
    int n = tid >> 3;
    int c = tid & 7;
    bool valid = (n < NN);
    if (!valid) n = NN - 1;             // keep warp whole for shfl
    int lane = threadIdx.x & 31;
    unsigned gmask = 0xFFu << (lane & 24);

    int m = min(__ldg(&g_cur[n]), CAP);
    // preload inv row: lane c holds inv[n][c + 8j], j=0..3 (coalesced)
    float iv0 = g_inv[n * RR + c];
    float iv1 = g_inv[n * RR + 8 + c];
    float iv2 = g_inv[n * RR + 16 + c];
    float iv3 = g_inv[n * RR + 24 + c];
    const int* ep = g_ep + n * CAP;

    float acc = 0.f;
    int k = 0;
    for (; k + 4 <= m; k += 4) {
        int4 a = __ldg((const int4*)(ep + k));
        int pk[4] = {a.x, a.y, a.z, a.w};
        float vv[4];
        #pragma unroll
        for (int j = 0; j < 4; j++) {
            int r = pk[j] >> 16, s = pk[j] & 0xFFFF;
            vv[j] = __ldg(&g_xw[((size_t)r * NN + s) * CC + c]);
        }
        #pragma unroll
        for (int j = 0; j < 4; j++) {
            int r = pk[j] >> 16;
            int jj = r >> 3;
            float sel = (jj == 0) ? iv0 : (jj == 1) ? iv1 : (jj == 2) ? iv2 : iv3;
            float iv = __shfl_sync(gmask, sel, r & 7, 8);
            acc += vv[j] * iv;
        }
    }
    for (; k < m; k++) {
        int v = __ldg(ep + k);
        int r = v >> 16, s = v & 0xFFFF;
        float xv = __ldg(&g_xw[((size_t)r * NN + s) * CC + c]);
        int jj = r >> 3;
        float sel = (jj == 0) ? iv0 : (jj == 1) ? iv1 : (jj == 2) ? iv2 : iv3;
        float iv = __shfl_sync(gmask, sel, r & 7, 8);
        acc += xv * iv;
    }

    // + x[n] @ root2 + b2
    const float4* xp = (const float4*)(g_x + (n << 4));
    float o = acc + sb2[c];
    #pragma unroll
    for (int i4 = 0; i4 < 4; i4++) {
        float4 xv = __ldg(&xp[i4]);
        o += xv.x * sr2[(i4 * 4 + 0) * CC + c];
        o += xv.y * sr2[(i4 * 4 + 1) * CC + c];
        o += xv.z * sr2[(i4 * 4 + 2) * CC + c];
        o += xv.w * sr2[(i4 * 4 + 3) * CC + c];
    }

    // log_softmax across the 8-lane class group
    float mx = o;
    #pragma unroll
    for (int d = 1; d < 8; d <<= 1)
        mx = fmaxf(mx, __shfl_xor_sync(0xFFFFFFFF, mx, d));
    float s = expf(o - mx);
    #pragma unroll
    for (int d = 1; d < 8; d <<= 1)
        s += __shfl_xor_sync(0xFFFFFFFF, s, d);
    if (valid) out[n * CC + c] = o - mx - logf(s);
}

// ---------------------------------------------------------------- launch
extern "C" void kernel_launch(void* const* d_in, const int* in_sizes, int n_in,
                              void* d_out, int out_size) {
    const int*   ei    = (const int*)  d_in[0];  // [2, E]
    const int*   et    = (const int*)  d_in[1];  // [E]
    const float* w1    = (const float*)d_in[2];  // [R, N, H]
    const float* root1 = (const float*)d_in[3];  // [N, H]
    const float* b1    = (const float*)d_in[4];  // [H]
    const float* w2    = (const float*)d_in[5];  // [R, H, C]
    const float* root2 = (const float*)d_in[6];  // [H, C]
    const float* b2    = (const float*)d_in[7];  // [C]
    float* out = (float*)d_out;                  // [N, C]

    k_zero  <<<(NN / 4 + 255) / 256, 256>>>();
    k_build <<<(EE + 255) / 256, 256>>>(ei, et);
    k_layer1<<<(NN * 16 + 255) / 256, 256>>>(w1, root1, b1);
    k_xw    <<<(RR * NN + 255) / 256, 256>>>(w2);            // idx 3 -> profiled
    k_layer2<<<(NN * 8 + 255) / 256, 256>>>(root2, b2, out);
}

// round 14
// speedup vs baseline: 1.4466x; 1.0665x over previous
#include <cuda_runtime.h>
#include <math.h>

// Problem constants (fixed-shape benchmark)
#define NN 50000
#define HH 16
#define RR 32
#define CC 8
#define EE 1600000
#define CAP 80   // slot capacity; deg ~ Poisson(32), P(exceed) ~ 1e-7, guarded

// Scratch (device globals; no allocation allowed)
__device__ int   g_cur[NN];          // per-node fill cursor (= degree after build)
__device__ int   g_ep[NN * CAP];     // 4B records: src | r<<16 (16 MB)
__device__ float g_inv[NN * RR];     // 1/max(cnt,1), produced by layer1 (12.8 MB)
__device__ float g_x[NN * HH];       // layer-1 node features
__device__ float g_xw[RR * NN * CC]; // per-relation transformed feats (51.2 MB)

// ---------------------------------------------------------------- (0) zero cursors
__global__ void k_zero() {
    int i = blockIdx.x * blockDim.x + threadIdx.x;
    if (i < NN / 4) ((int4*)g_cur)[i] = make_int4(0, 0, 0, 0);
}

// ---------------------------------------------------------------- (1) build slotted CSR (1 atomic + 1 store per edge)
__global__ void k_build(const int* __restrict__ ei, const int* __restrict__ et) {
    int e = blockIdx.x * blockDim.x + threadIdx.x;
    if (e >= EE) return;
    int src = __ldg(ei + e);
    int dst = __ldg(ei + EE + e);
    int r   = __ldg(et + e);
    int pos = atomicAdd(&g_cur[dst], 1);
    if (pos < CAP) g_ep[dst * CAP + pos] = src | (r << 16);
}

// ---------------------------------------------------------------- (2) layer 1: count + gather, 16 lanes/node, fused act
__global__ void __launch_bounds__(256)
k_layer1(const float* __restrict__ w1, const float* __restrict__ root1,
         const float* __restrict__ b1) {
    int tid = blockIdx.x * 256 + threadIdx.x;
    int n = tid >> 4;
    int f = tid & 15;
    if (n >= NN) return;
    int lane = threadIdx.x & 31;
    unsigned gmask = (lane & 16) ? 0xFFFF0000u : 0x0000FFFFu;

    int m = min(__ldg(&g_cur[n]), CAP);
    const int* ep = g_ep + n * CAP;

    // pass A: per-lane relation histogram (lane f counts r==f and r==f+16)
    int clo = 0, chi = 0;
    int k = 0;
    for (; k + 4 <= m; k += 4) {
        int4 a = __ldg((const int4*)(ep + k));
        int r0 = a.x >> 16, r1 = a.y >> 16, r2 = a.z >> 16, r3 = a.w >> 16;
        clo += (r0 == f) + (r1 == f) + (r2 == f) + (r3 == f);
        int fh = f + 16;
        chi += (r0 == fh) + (r1 == fh) + (r2 == fh) + (r3 == fh);
    }
    for (; k < m; k++) {
        int r = __ldg(ep + k) >> 16;
        clo += (r == f);
        chi += (r == f + 16);
    }
    float inv_lo = __frcp_rn(fmaxf((float)clo, 1.f));
    float inv_hi = __frcp_rn(fmaxf((float)chi, 1.f));
    g_inv[n * RR + f]      = inv_lo;   // coalesced; consumed by layer2
    g_inv[n * RR + 16 + f] = inv_hi;

    // pass B: w1 gather + weighted accumulate (records now L1-hot)
    float acc = 0.f;
    k = 0;
    for (; k + 8 <= m; k += 8) {
        int4 a = __ldg((const int4*)(ep + k));
        int4 b = __ldg((const int4*)(ep + k + 4));
        int pk[8] = {a.x, a.y, a.z, a.w, b.x, b.y, b.z, b.w};
        float wv[8];
        #pragma unroll
        for (int j = 0; j < 8; j++) {
            int r = pk[j] >> 16, s = pk[j] & 0xFFFF;
            wv[j] = __ldg(&w1[((r * NN + s) << 4) + f]);
        }
        #pragma unroll
        for (int j = 0; j < 8; j++) {
            int r = pk[j] >> 16;
            float iv = __shfl_sync(gmask, (r < 16) ? inv_lo : inv_hi, r & 15, 16);
            acc += wv[j] * iv;
        }
    }
    for (; k < m; k++) {
        int v = __ldg(ep + k);
        int r = v >> 16, s = v & 0xFFFF;
        float w = __ldg(&w1[((r * NN + s) << 4) + f]);
        float iv = __shfl_sync(gmask, (r < 16) ? inv_lo : inv_hi, r & 15, 16);
        acc += w * iv;
    }
    float v = acc + __ldg(&root1[(n << 4) + f]) + __ldg(&b1[f]);
    g_x[(n << 4) + f] = fmaxf(v, 0.f);
}

// ---------------------------------------------------------------- (3) xw: block-constant relation, register-resident w2
// xw[r, n, :] = x[n, :] @ w2[r].  Thread = (node-slot, class-half).
__global__ void __launch_bounds__(256)
k_xw(const float* __restrict__ w2) {
    int r     = blockIdx.x >> 3;         // 32 relations
    int chunk = blockIdx.x & 7;          // 8 chunks per relation
    int half  = threadIdx.x & 1;         // class half: c in [half*4, half*4+4)
    int nslot = threadIdx.x >> 1;        // 128 node slots per block

    // w2[r][h][half*4 ..] -> registers (64 floats), uniform per half
    float wr[HH][4];
    #pragma unroll
    for (int h = 0; h < HH; h++) {
        float4 wv = __ldg((const float4*)(w2 + (r * HH + h) * CC + half * 4));
        wr[h][0] = wv.x; wr[h][1] = wv.y; wr[h][2] = wv.z; wr[h][3] = wv.w;
    }

    float4* xwout = (float4*)g_xw;
    for (int n = chunk * 128 + nslot; n < NN; n += 1024) {
        const float4* xp = (const float4*)(g_x + n * HH);
        float4 x0 = __ldg(&xp[0]), x1 = __ldg(&xp[1]);
        float4 x2 = __ldg(&xp[2]), x3 = __ldg(&xp[3]);
        float xs[HH] = {x0.x, x0.y, x0.z, x0.w, x1.x, x1.y, x1.z, x1.w,
                        x2.x, x2.y, x2.z, x2.w, x3.x, x3.y, x3.z, x3.w};
        float a0 = 0.f, a1 = 0.f, a2 = 0.f, a3 = 0.f;
        #pragma unroll
        for (int h = 0; h < HH; h++) {
            a0 += xs[h] * wr[h][0];
            a1 += xs[h] * wr[h][1];
            a2 += xs[h] * wr[h][2];
            a3 += xs[h] * wr[h][3];
        }
        // float4 index (r*NN+n)*2+half : contiguous across (nslot,half) -> coalesced
        xwout[((size_t)r * NN + n) * 2 + half] = make_float4(a0, a1, a2, a3);
    }
}

// ---------------------------------------------------------------- (4) layer 2: xw gather, 8 lanes/node, fused epilogue
__global__ void __launch_bounds__(256)
k_layer2(const float* __restrict__ root2, const float* __restrict__ b2,
         float* __restrict__ out) {
    __shared__ float sr2[HH * CC];
    __shared__ float sb2[CC];
    if (threadIdx.x < HH * CC) sr2[threadIdx.x] = root2[threadIdx.x];
    if (threadIdx.x < CC) sb2[threadIdx.x] = b2[threadIdx.x];
    __syncthreads();

    int tid = blockIdx.x * 256 + threadIdx.x;
    int n = tid >> 3;
    int c = tid & 7;
    bool valid = (n < NN);
    if (!valid) n = NN - 1;             // keep warp whole for shfl
    int lane = threadIdx.x & 31;
    unsigned gmask = 0xFFu << (lane & 24);

    int m = min(__ldg(&g_cur[n]), CAP);
    // preload inv row: lane c holds inv[n][c + 8j], j=0..3 (coalesced)
    float iv0 = g_inv[n * RR + c];
    float iv1 = g_inv[n * RR + 8 + c];
    float iv2 = g_inv[n * RR + 16 + c];
    float iv3 = g_inv[n * RR + 24 + c];
    const int* ep = g_ep + n * CAP;

    float acc = 0.f;
    int k = 0;
    for (; k + 4 <= m; k += 4) {
        int4 a = __ldg((const int4*)(ep + k));
        int pk[4] = {a.x, a.y, a.z, a.w};
        float vv[4];
        #pragma unroll
        for (int j = 0; j < 4; j++) {
            int r = pk[j] >> 16, s = pk[j] & 0xFFFF;
            vv[j] = __ldg(&g_xw[((size_t)r * NN + s) * CC + c]);
        }
        #pragma unroll
        for (int j = 0; j < 4; j++) {
            int r = pk[j] >> 16;
            int jj = r >> 3;
            float sel = (jj == 0) ? iv0 : (jj == 1) ? iv1 : (jj == 2) ? iv2 : iv3;
            float iv = __shfl_sync(gmask, sel, r & 7, 8);
            acc += vv[j] * iv;
        }
    }
    for (; k < m; k++) {
        int v = __ldg(ep + k);
        int r = v >> 16, s = v & 0xFFFF;
        float xv = __ldg(&g_xw[((size_t)r * NN + s) * CC + c]);
        int jj = r >> 3;
        float sel = (jj == 0) ? iv0 : (jj == 1) ? iv1 : (jj == 2) ? iv2 : iv3;
        float iv = __shfl_sync(gmask, sel, r & 7, 8);
        acc += xv * iv;
    }

    // + x[n] @ root2 + b2
    const float4* xp = (const float4*)(g_x + (n << 4));
    float o = acc + sb2[c];
    #pragma unroll
    for (int i4 = 0; i4 < 4; i4++) {
        float4 xv = __ldg(&xp[i4]);
        o += xv.x * sr2[(i4 * 4 + 0) * CC + c];
        o += xv.y * sr2[(i4 * 4 + 1) * CC + c];
        o += xv.z * sr2[(i4 * 4 + 2) * CC + c];
        o += xv.w * sr2[(i4 * 4 + 3) * CC + c];
    }

    // log_softmax across the 8-lane class group
    float mx = o;
    #pragma unroll
    for (int d = 1; d < 8; d <<= 1)
        mx = fmaxf(mx, __shfl_xor_sync(0xFFFFFFFF, mx, d));
    float s = expf(o - mx);
    #pragma unroll
    for (int d = 1; d < 8; d <<= 1)
        s += __shfl_xor_sync(0xFFFFFFFF, s, d);
    if (valid) out[n * CC + c] = o - mx - logf(s);
}

// ---------------------------------------------------------------- launch
extern "C" void kernel_launch(void* const* d_in, const int* in_sizes, int n_in,
                              void* d_out, int out_size) {
    const int*   ei    = (const int*)  d_in[0];  // [2, E]
    const int*   et    = (const int*)  d_in[1];  // [E]
    const float* w1    = (const float*)d_in[2];  // [R, N, H]
    const float* root1 = (const float*)d_in[3];  // [N, H]
    const float* b1    = (const float*)d_in[4];  // [H]
    const float* w2    = (const float*)d_in[5];  // [R, H, C]
    const float* root2 = (const float*)d_in[6];  // [H, C]
    const float* b2    = (const float*)d_in[7];  // [C]
    float* out = (float*)d_out;                  // [N, C]

    k_zero  <<<(NN / 4 + 255) / 256, 256>>>();
    k_build <<<(EE + 255) / 256, 256>>>(ei, et);
    k_layer1<<<(NN * 16 + 255) / 256, 256>>>(w1, root1, b1);
    k_xw    <<<256, 256>>>(w2);                              // idx 3 -> profiled
    k_layer2<<<(NN * 8 + 255) / 256, 256>>>(root2, b2, out);
}

// round 16
// speedup vs baseline: 1.5195x; 1.0504x over previous
#include <cuda_runtime.h>
#include <math.h>

// Problem constants (fixed-shape benchmark)
#define NN 50000
#define HH 16
#define RR 32
#define CC 8
#define EE 1600000
#define CAP 80   // slot capacity; deg ~ Poisson(32), P(exceed) ~ 1e-7, guarded

// Scratch (device globals; no allocation allowed)
__device__ int   g_cur[NN];          // per-node fill cursor (= degree after build)
__device__ int   g_ep[NN * CAP];     // 4B records: src | r<<16 (16 MB)
__device__ float g_inv[NN * RR];     // 1/max(cnt,1), produced by layer1 (12.8 MB)
__device__ float g_x[NN * HH];       // layer-1 node features
__device__ float g_xw[RR * NN * CC]; // per-relation transformed feats (51.2 MB)

// ---------------------------------------------------------------- (0) zero cursors
__global__ void k_zero() {
    int i = blockIdx.x * blockDim.x + threadIdx.x;
    if (i < NN / 4) ((int4*)g_cur)[i] = make_int4(0, 0, 0, 0);
}

// ---------------------------------------------------------------- (1) build slotted CSR (1 atomic + 1 store per edge)
__global__ void k_build(const int* __restrict__ ei, const int* __restrict__ et) {
    int e = blockIdx.x * blockDim.x + threadIdx.x;
    if (e >= EE) return;
    int src = __ldg(ei + e);
    int dst = __ldg(ei + EE + e);
    int r   = __ldg(et + e);
    int pos = atomicAdd(&g_cur[dst], 1);
    if (pos < CAP) g_ep[dst * CAP + pos] = src | (r << 16);
}

// ---------------------------------------------------------------- (2) layer 1: count + gather, 16 lanes/node, fused act
__global__ void __launch_bounds__(256)
k_layer1(const float* __restrict__ w1, const float* __restrict__ root1,
         const float* __restrict__ b1) {
    int tid = blockIdx.x * 256 + threadIdx.x;
    int n = tid >> 4;
    int f = tid & 15;
    if (n >= NN) return;
    int lane = threadIdx.x & 31;
    unsigned gmask = (lane & 16) ? 0xFFFF0000u : 0x0000FFFFu;

    int m = min(__ldg(&g_cur[n]), CAP);
    const int* ep = g_ep + n * CAP;

    // pass A: per-lane relation histogram (lane f counts r==f and r==f+16)
    int clo = 0, chi = 0;
    int k = 0;
    for (; k + 4 <= m; k += 4) {
        int4 a = __ldg((const int4*)(ep + k));
        int r0 = a.x >> 16, r1 = a.y >> 16, r2 = a.z >> 16, r3 = a.w >> 16;
        clo += (r0 == f) + (r1 == f) + (r2 == f) + (r3 == f);
        int fh = f + 16;
        chi += (r0 == fh) + (r1 == fh) + (r2 == fh) + (r3 == fh);
    }
    for (; k < m; k++) {
        int r = __ldg(ep + k) >> 16;
        clo += (r == f);
        chi += (r == f + 16);
    }
    float inv_lo = __frcp_rn(fmaxf((float)clo, 1.f));
    float inv_hi = __frcp_rn(fmaxf((float)chi, 1.f));
    g_inv[n * RR + f]      = inv_lo;   // coalesced; consumed by layer2
    g_inv[n * RR + 16 + f] = inv_hi;

    // pass B: w1 gather + weighted accumulate (records now L1-hot)
    float acc = 0.f;
    k = 0;
    for (; k + 8 <= m; k += 8) {
        int4 a = __ldg((const int4*)(ep + k));
        int4 b = __ldg((const int4*)(ep + k + 4));
        int pk[8] = {a.x, a.y, a.z, a.w, b.x, b.y, b.z, b.w};
        float wv[8];
        #pragma unroll
        for (int j = 0; j < 8; j++) {
            int r = pk[j] >> 16, s = pk[j] & 0xFFFF;
            wv[j] = __ldg(&w1[((r * NN + s) << 4) + f]);
        }
        #pragma unroll
        for (int j = 0; j < 8; j++) {
            int r = pk[j] >> 16;
            float iv = __shfl_sync(gmask, (r < 16) ? inv_lo : inv_hi, r & 15, 16);
            acc += wv[j] * iv;
        }
    }
    for (; k < m; k++) {
        int v = __ldg(ep + k);
        int r = v >> 16, s = v & 0xFFFF;
        float w = __ldg(&w1[((r * NN + s) << 4) + f]);
        float iv = __shfl_sync(gmask, (r < 16) ? inv_lo : inv_hi, r & 15, 16);
        acc += w * iv;
    }
    float v = acc + __ldg(&root1[(n << 4) + f]) + __ldg(&b1[f]);
    g_x[(n << 4) + f] = fmaxf(v, 0.f);
}

// ---------------------------------------------------------------- (3) xw: block-constant relation, 2-class register w2 slice
// xw[r, n, :] = x[n, :] @ w2[r].  Thread = (node-slot, class-pair).
__global__ void __launch_bounds__(256)
k_xw(const float* __restrict__ w2) {
    int r     = blockIdx.x >> 4;         // 32 relations
    int chunk = blockIdx.x & 15;         // 16 chunks per relation
    int cpair = threadIdx.x & 3;         // classes [cpair*2, cpair*2+1]
    int nslot = threadIdx.x >> 2;        // 64 node slots per block

    // w2[r][h][cpair*2 ..] -> 32 registers
    float wa[HH], wb[HH];
    #pragma unroll
    for (int h = 0; h < HH; h++) {
        float2 wv = __ldg((const float2*)(w2 + (r * HH + h) * CC + cpair * 2));
        wa[h] = wv.x; wb[h] = wv.y;
    }

    float2* xwout = (float2*)g_xw;
    for (int n = chunk * 64 + nslot; n < NN; n += 1024) {
        const float4* xp = (const float4*)(g_x + n * HH);
        float4 x0 = __ldg(&xp[0]), x1 = __ldg(&xp[1]);
        float4 x2 = __ldg(&xp[2]), x3 = __ldg(&xp[3]);
        float xs[HH] = {x0.x, x0.y, x0.z, x0.w, x1.x, x1.y, x1.z, x1.w,
                        x2.x, x2.y, x2.z, x2.w, x3.x, x3.y, x3.z, x3.w};
        float a = 0.f, b = 0.f;
        #pragma unroll
        for (int h = 0; h < HH; h++) {
            a += xs[h] * wa[h];
            b += xs[h] * wb[h];
        }
        // float2 index (r*NN+n)*4 + cpair : contiguous across (nslot,cpair) -> coalesced
        xwout[((size_t)r * NN + n) * 4 + cpair] = make_float2(a, b);
    }
}

// ---------------------------------------------------------------- (4) layer 2: xw gather, 8 lanes/node, fused epilogue
__global__ void __launch_bounds__(256)
k_layer2(const float* __restrict__ root2, const float* __restrict__ b2,
         float* __restrict__ out) {
    __shared__ float sr2[HH * CC];
    __shared__ float sb2[CC];
    if (threadIdx.x < HH * CC) sr2[threadIdx.x] = root2[threadIdx.x];
    if (threadIdx.x < CC) sb2[threadIdx.x] = b2[threadIdx.x];
    __syncthreads();

    int tid = blockIdx.x * 256 + threadIdx.x;
    int n = tid >> 3;
    int c = tid & 7;
    bool valid = (n < NN);
    if (!valid) n = NN - 1;             // keep warp whole for shfl
    int lane = threadIdx.x & 31;
    unsigned gmask = 0xFFu << (lane & 24);

    int m = min(__ldg(&g_cur[n]), CAP);
    // preload inv row: lane c holds inv[n][c + 8j], j=0..3 (coalesced)
    float iv0 = g_inv[n * RR + c];
    float iv1 = g_inv[n * RR + 8 + c];
    float iv2 = g_inv[n * RR + 16 + c];
    float iv3 = g_inv[n * RR + 24 + c];
    const int* ep = g_ep + n * CAP;

    float acc = 0.f;
    int k = 0;
    for (; k + 8 <= m; k += 8) {
        int4 a = __ldg((const int4*)(ep + k));
        int4 b = __ldg((const int4*)(ep + k + 4));
        int pk[8] = {a.x, a.y, a.z, a.w, b.x, b.y, b.z, b.w};
        float vv[8];
        #pragma unroll
        for (int j = 0; j < 8; j++) {
            int r = pk[j] >> 16, s = pk[j] & 0xFFFF;
            vv[j] = __ldg(&g_xw[((size_t)r * NN + s) * CC + c]);
        }
        #pragma unroll
        for (int j = 0; j < 8; j++) {
            int r = pk[j] >> 16;
            int jj = r >> 3;
            float sel = (jj == 0) ? iv0 : (jj == 1) ? iv1 : (jj == 2) ? iv2 : iv3;
            float iv = __shfl_sync(gmask, sel, r & 7, 8);
            acc += vv[j] * iv;
        }
    }
    for (; k < m; k++) {
        int v = __ldg(ep + k);
        int r = v >> 16, s = v & 0xFFFF;
        float xv = __ldg(&g_xw[((size_t)r * NN + s) * CC + c]);
        int jj = r >> 3;
        float sel = (jj == 0) ? iv0 : (jj == 1) ? iv1 : (jj == 2) ? iv2 : iv3;
        float iv = __shfl_sync(gmask, sel, r & 7, 8);
        acc += xv * iv;
    }

    // + x[n] @ root2 + b2
    const float4* xp = (const float4*)(g_x + (n << 4));
    float o = acc + sb2[c];
    #pragma unroll
    for (int i4 = 0; i4 < 4; i4++) {
        float4 xv = __ldg(&xp[i4]);
        o += xv.x * sr2[(i4 * 4 + 0) * CC + c];
        o += xv.y * sr2[(i4 * 4 + 1) * CC + c];
        o += xv.z * sr2[(i4 * 4 + 2) * CC + c];
        o += xv.w * sr2[(i4 * 4 + 3) * CC + c];
    }

    // log_softmax across the 8-lane class group
    float mx = o;
    #pragma unroll
    for (int d = 1; d < 8; d <<= 1)
        mx = fmaxf(mx, __shfl_xor_sync(0xFFFFFFFF, mx, d));
    float s = expf(o - mx);
    #pragma unroll
    for (int d = 1; d < 8; d <<= 1)
        s += __shfl_xor_sync(0xFFFFFFFF, s, d);
    if (valid) out[n * CC + c] = o - mx - logf(s);
}

// ---------------------------------------------------------------- launch
extern "C" void kernel_launch(void* const* d_in, const int* in_sizes, int n_in,
                              void* d_out, int out_size) {
    const int*   ei    = (const int*)  d_in[0];  // [2, E]
    const int*   et    = (const int*)  d_in[1];  // [E]
    const float* w1    = (const float*)d_in[2];  // [R, N, H]
    const float* root1 = (const float*)d_in[3];  // [N, H]
    const float* b1    = (const float*)d_in[4];  // [H]
    const float* w2    = (const float*)d_in[5];  // [R, H, C]
    const float* root2 = (const float*)d_in[6];  // [H, C]
    const float* b2    = (const float*)d_in[7];  // [C]
    float* out = (float*)d_out;                  // [N, C]

    k_zero  <<<(NN / 4 + 255) / 256, 256>>>();
    k_build <<<(EE + 255) / 256, 256>>>(ei, et);
    k_layer1<<<(NN * 16 + 255) / 256, 256>>>(w1, root1, b1);
    k_xw    <<<512, 256>>>(w2);                              // idx 3 -> profiled
    k_layer2<<<(NN * 8 + 255) / 256, 256>>>(root2, b2, out);
}